// round 2
// baseline (speedup 1.0000x reference)
#include <cuda_runtime.h>

// KANLayer: out[r,o] = sum_{i,n} tanh(h[i,n,o]*x[r,i] + b[i,n,o]) * w[i,n,o]
// r = b*S+s, R=2048, I=64, N=16, O=64.
// tanh(z) = 1 - 2/(exp(2z)+1) = 1 - 2*r,  r = 1/(2^m + 1), m = 2*log2(e)*z.
// out = Wsum - 2 * sum w*r,  Wsum = sum w  (hoisted).
// Dual-pipe: row A uses MUFU.RCP, row B uses bit-seed + Newton (FMA pipe).

#define I_DIM 64
#define N_DIM 16
#define O_DIM 64
#define NROWS 2048
#define O_TILE 8
#define THREADS 512
#define RBLKS 18
#define NBLOCKS (8 * RBLKS)                  // 144 blocks, 1 per SM
#define E_TOTAL (I_DIM * N_DIM)              // 1024
#define SMEM_BYTES (E_TOTAL * O_TILE * 16)   // 8192 float4 = 128KB
#define C2L 2.885390081777927f               // 2 * log2(e)

__device__ __forceinline__ float ex2f(float m) {
    float u; asm("ex2.approx.f32 %0, %1;" : "=f"(u) : "f"(m)); return u;
}
__device__ __forceinline__ float rcpf(float d) {
    float r; asm("rcp.approx.f32 %0, %1;" : "=f"(r) : "f"(d)); return r;
}
// Reciprocal on the FMA pipe: bit-trick seed (~6% err) + 3 Newton steps (exact).
__device__ __forceinline__ float rcp_newton(float d) {
    float r = __int_as_float(0x7EF127EA - __float_as_int(d));
    r = r * fmaf(-d, r, 2.0f);
    r = r * fmaf(-d, r, 2.0f);
    r = r * fmaf(-d, r, 2.0f);
    return r;
}

template <bool DUAL>
__device__ __forceinline__ void process_rows(
    const float4* __restrict__ sp,   // smem params: [e][ol] float4(hc,bc,w,0)
    const float* __restrict__ gx,
    float* __restrict__ gout,
    int ra, int rb, int ol, int o0)
{
    float acc_a = 0.0f, acc_b = 0.0f, accW = 0.0f;
    const float4* xa_ptr = reinterpret_cast<const float4*>(gx + ra * I_DIM);
    const float4* xb_ptr = reinterpret_cast<const float4*>(gx + (DUAL ? rb : ra) * I_DIM);
    const float4* pp = sp + ol;

    #pragma unroll 1
    for (int ib = 0; ib < I_DIM / 4; ib++) {      // 16 iterations, 4 i each
        float4 xa4 = __ldg(xa_ptr + ib);
        float4 xb4 = DUAL ? __ldg(xb_ptr + ib) : xa4;
        float xsa[4] = {xa4.x, xa4.y, xa4.z, xa4.w};
        float xsb[4] = {xb4.x, xb4.y, xb4.z, xb4.w};

        #pragma unroll
        for (int ii = 0; ii < 4; ii++) {
            float xa = xsa[ii];
            float xb = xsb[ii];
            #pragma unroll
            for (int n = 0; n < N_DIM; n++) {
                int e = (ib * 4 + ii) * N_DIM + n;
                float4 p = pp[e * O_TILE];        // LDS.128, broadcast-friendly
                accW += p.z;
                // row A: MUFU route
                float ma = fmaf(p.x, xa, p.y);
                float da = ex2f(ma) + 1.0f;
                float ra_ = rcpf(da);
                acc_a = fmaf(p.z, ra_, acc_a);
                if (DUAL) {
                    // row B: FMA-pipe Newton route (clamp keeps d finite)
                    float mb = fminf(fmaf(p.x, xb, p.y), 30.0f);
                    float db = ex2f(mb) + 1.0f;
                    float rb_ = rcp_newton(db);
                    acc_b = fmaf(p.z, rb_, acc_b);
                }
            }
        }
    }

    gout[ra * O_DIM + o0 + ol] = fmaf(-2.0f, acc_a, accW);
    if (DUAL)
        gout[rb * O_DIM + o0 + ol] = fmaf(-2.0f, acc_b, accW);
}

__global__ void __launch_bounds__(THREADS, 1)
kan_kernel(const float* __restrict__ gx, const float* __restrict__ gw,
           const float* __restrict__ gh, const float* __restrict__ gb,
           float* __restrict__ gout)
{
    extern __shared__ float4 sp[];    // [E_TOTAL][O_TILE]

    const int tid  = threadIdx.x;
    const int ot   = blockIdx.x % 8;
    const int rblk = blockIdx.x / 8;
    const int o0   = ot * O_TILE;

    // ---- stage params once: (h*C, b*C, w, 0) ----
    #pragma unroll 4
    for (int idx = tid; idx < E_TOTAL * O_TILE; idx += THREADS) {
        int e  = idx / O_TILE;
        int olp = idx % O_TILE;
        int g  = e * O_DIM + o0 + olp;
        sp[idx] = make_float4(gh[g] * C2L, gb[g] * C2L, gw[g], 0.0f);
    }
    __syncthreads();

    const int ol = tid & (O_TILE - 1);
    const int rg = tid >> 3;                       // 0..63

    const int r_start = (rblk * NROWS) / RBLKS;
    const int r_end   = ((rblk + 1) * NROWS) / RBLKS;
    const int cnt     = r_end - r_start;           // 113 or 114

    const int ra = r_start + rg;                   // always valid (cnt >= 64)
    const int rb = r_start + 64 + rg;

    if (rb < r_end)
        process_rows<true >(sp, gx, gout, ra, rb, ol, o0);
    else
        process_rows<false>(sp, gx, gout, ra, ra, ol, o0);
}

extern "C" void kernel_launch(void* const* d_in, const int* in_sizes, int n_in,
                              void* d_out, int out_size) {
    const float* x = (const float*)d_in[0];
    const float* w = (const float*)d_in[1];
    const float* h = (const float*)d_in[2];
    const float* b = (const float*)d_in[3];
    float* out = (float*)d_out;

    cudaFuncSetAttribute(kan_kernel, cudaFuncAttributeMaxDynamicSharedMemorySize,
                         SMEM_BYTES);
    kan_kernel<<<NBLOCKS, THREADS, SMEM_BYTES>>>(x, w, h, b, out);
}

// round 3
// speedup vs baseline: 1.6758x; 1.6758x over previous
#include <cuda_runtime.h>

// KANLayer: out[r,o] = sum_{i,n} tanh(h[i,n,o]*x[r,i] + b[i,n,o]) * w[i,n,o]
// r = b*S+s, R=2048, I=64, N=16, O=64.
// Core math per element: FFMA (z) -> MUFU.TANH -> FFMA (acc). MUFU-bound.

#define I_DIM 64
#define N_DIM 16
#define O_DIM 64
#define NROWS 2048
#define O_TILE 8
#define THREADS 512
#define RBLKS 18
#define NBLOCKS (8 * RBLKS)                  // 144 blocks, 1 per SM
#define E_TOTAL (I_DIM * N_DIM)              // 1024
#define SMEM_BYTES (E_TOTAL * O_TILE * 16)   // 8192 float4 = 128KB

__device__ __forceinline__ float tanh_hw(float z) {
    float t;
    asm("tanh.approx.f32 %0, %1;" : "=f"(t) : "f"(z));
    return t;
}

template <bool DUAL>
__device__ __forceinline__ void process_rows(
    const float4* __restrict__ sp,   // smem params: [e][ol] float4(h,b,w,0)
    const float* __restrict__ gx,
    float* __restrict__ gout,
    int ra, int rb, int ol, int o0)
{
    float acc_a = 0.0f, acc_b = 0.0f;
    const float4* xa_ptr = reinterpret_cast<const float4*>(gx + ra * I_DIM);
    const float4* xb_ptr = reinterpret_cast<const float4*>(gx + (DUAL ? rb : ra) * I_DIM);

    const float4* p_it = sp + ol;    // walks by O_TILE per e -> single IADD

    #pragma unroll 1
    for (int ib = 0; ib < I_DIM / 4; ib++) {      // 16 outer iters, 4 i each
        float4 xa4 = __ldg(xa_ptr + ib);
        float4 xb4 = DUAL ? __ldg(xb_ptr + ib) : xa4;
        float xsa[4] = {xa4.x, xa4.y, xa4.z, xa4.w};
        float xsb[4] = {xb4.x, xb4.y, xb4.z, xb4.w};

        #pragma unroll
        for (int ii = 0; ii < 4; ii++) {
            float xa = xsa[ii];
            float xb = xsb[ii];
            #pragma unroll
            for (int n = 0; n < N_DIM; n++) {
                float4 p = *p_it;  p_it += O_TILE;   // LDS.128, conflict-free
                float ta = tanh_hw(fmaf(p.x, xa, p.y));
                acc_a = fmaf(ta, p.z, acc_a);
                if (DUAL) {
                    float tb = tanh_hw(fmaf(p.x, xb, p.y));
                    acc_b = fmaf(tb, p.z, acc_b);
                }
            }
        }
    }

    gout[ra * O_DIM + o0 + ol] = acc_a;
    if (DUAL)
        gout[rb * O_DIM + o0 + ol] = acc_b;
}

__global__ void __launch_bounds__(THREADS, 1)
kan_kernel(const float* __restrict__ gx, const float* __restrict__ gw,
           const float* __restrict__ gh, const float* __restrict__ gb,
           float* __restrict__ gout)
{
    extern __shared__ float4 sp[];    // [E_TOTAL][O_TILE]

    const int tid  = threadIdx.x;
    const int ot   = blockIdx.x % 8;
    const int rblk = blockIdx.x / 8;
    const int o0   = ot * O_TILE;

    // ---- stage params once: (h, b, w, 0) ----
    #pragma unroll 4
    for (int idx = tid; idx < E_TOTAL * O_TILE; idx += THREADS) {
        int e   = idx / O_TILE;
        int olp = idx % O_TILE;
        int g   = e * O_DIM + o0 + olp;
        sp[idx] = make_float4(gh[g], gb[g], gw[g], 0.0f);
    }
    __syncthreads();

    const int ol = tid & (O_TILE - 1);
    const int rg = tid >> 3;                       // 0..63

    const int r_start = (rblk * NROWS) / RBLKS;
    const int r_end   = ((rblk + 1) * NROWS) / RBLKS;

    const int ra = r_start + rg;                   // always valid (>=64 rows/blk)
    const int rb = r_start + 64 + rg;

    if (rb < r_end)
        process_rows<true >(sp, gx, gout, ra, rb, ol, o0);
    else
        process_rows<false>(sp, gx, gout, ra, ra, ol, o0);
}

extern "C" void kernel_launch(void* const* d_in, const int* in_sizes, int n_in,
                              void* d_out, int out_size) {
    const float* x = (const float*)d_in[0];
    const float* w = (const float*)d_in[1];
    const float* h = (const float*)d_in[2];
    const float* b = (const float*)d_in[3];
    float* out = (float*)d_out;

    cudaFuncSetAttribute(kan_kernel, cudaFuncAttributeMaxDynamicSharedMemorySize,
                         SMEM_BYTES);
    kan_kernel<<<NBLOCKS, THREADS, SMEM_BYTES>>>(x, w, h, b, out);
}

// round 4
// speedup vs baseline: 2.1480x; 1.2818x over previous
#include <cuda_runtime.h>

// KANLayer: out[r,o] = sum_{i,n} tanh(h[i,n,o]*x[r,i] + b[i,n,o]) * w[i,n,o]
// R=2048 rows, I=64, N=16, O=64. MUFU.TANH core: FFMA -> MUFU.TANH -> FFMA.
// Concurrency plan: 1024 thr/block (32 warps/SM), e-reduction split 4 ways
// across threads, 4 rows per thread per LDS.128 -> MUFU pipe saturation.

#define I_DIM 64
#define N_DIM 16
#define O_DIM 64
#define NROWS 2048

#define O_TILE 8
#define RBLKS 16
#define NBLOCKS (8 * RBLKS)        // 128 blocks
#define THREADS 1024               // 8 ol x 32 rg x 4 es
#define ROWS_PER_BLOCK 128         // 32 rg x 4 rows
#define ES 4
#define E_PER 256                  // e's per es-slice (16 i values)
#define E_TOTAL (I_DIM * N_DIM)    // 1024

#define PARAM_FLOAT4 (E_TOTAL * O_TILE)          // 8192 float4 = 128KB
#define RED_FLOATS (ROWS_PER_BLOCK * O_TILE * ES) // 4096 floats = 16KB
#define SMEM_BYTES (PARAM_FLOAT4 * 16 + RED_FLOATS * 4)

__device__ __forceinline__ float tanh_hw(float z) {
    float t;
    asm("tanh.approx.f32 %0, %1;" : "=f"(t) : "f"(z));
    return t;
}

__global__ void __launch_bounds__(THREADS, 1)
kan_kernel(const float* __restrict__ gx, const float* __restrict__ gw,
           const float* __restrict__ gh, const float* __restrict__ gb,
           float* __restrict__ gout)
{
    extern __shared__ float smem_raw[];
    float4* sp  = reinterpret_cast<float4*>(smem_raw);      // [E_TOTAL][O_TILE]
    float*  red = smem_raw + PARAM_FLOAT4 * 4;               // [128][8][4]

    const int tid  = threadIdx.x;
    const int ot   = blockIdx.x & 7;
    const int rblk = blockIdx.x >> 3;
    const int o0   = ot * O_TILE;
    const int row0 = rblk * ROWS_PER_BLOCK;

    // ---- stage params: sp[e][ol] = (h, b, w, 0) for this o-tile ----
    #pragma unroll 8
    for (int idx = tid; idx < E_TOTAL * O_TILE; idx += THREADS) {
        int e   = idx >> 3;            // O_TILE == 8
        int olp = idx & 7;
        int g   = e * O_DIM + o0 + olp;
        sp[idx] = make_float4(gh[g], gb[g], gw[g], 0.0f);
    }
    __syncthreads();

    const int ol = tid & 7;
    const int rg = (tid >> 3) & 31;    // 0..31, owns 4 rows
    const int es = tid >> 8;           // 0..3, owns e in [es*256, es*256+256)

    const int r0 = row0 + rg * 4;      // 4 consecutive rows

    float acc[4] = {0.0f, 0.0f, 0.0f, 0.0f};

    // x rows as float4; this thread needs i in [es*16, es*16+16) -> 4 float4/row
    const float4* xr0 = reinterpret_cast<const float4*>(gx + (r0 + 0) * I_DIM) + es * 4;
    const float4* xr1 = reinterpret_cast<const float4*>(gx + (r0 + 1) * I_DIM) + es * 4;
    const float4* xr2 = reinterpret_cast<const float4*>(gx + (r0 + 2) * I_DIM) + es * 4;
    const float4* xr3 = reinterpret_cast<const float4*>(gx + (r0 + 3) * I_DIM) + es * 4;

    const float4* p_it = sp + es * E_PER * O_TILE + ol;

    #pragma unroll 1
    for (int ib = 0; ib < 4; ib++) {          // 4 i's per ib
        float4 x0 = __ldg(xr0 + ib);
        float4 x1 = __ldg(xr1 + ib);
        float4 x2 = __ldg(xr2 + ib);
        float4 x3 = __ldg(xr3 + ib);
        float xs0[4] = {x0.x, x0.y, x0.z, x0.w};
        float xs1[4] = {x1.x, x1.y, x1.z, x1.w};
        float xs2[4] = {x2.x, x2.y, x2.z, x2.w};
        float xs3[4] = {x3.x, x3.y, x3.z, x3.w};

        #pragma unroll
        for (int ii = 0; ii < 4; ii++) {
            float xa = xs0[ii], xb = xs1[ii], xc = xs2[ii], xd = xs3[ii];
            #pragma unroll
            for (int n = 0; n < N_DIM; n++) {
                float4 p = *p_it;  p_it += O_TILE;   // LDS.128, broadcast x4
                acc[0] = fmaf(tanh_hw(fmaf(p.x, xa, p.y)), p.z, acc[0]);
                acc[1] = fmaf(tanh_hw(fmaf(p.x, xb, p.y)), p.z, acc[1]);
                acc[2] = fmaf(tanh_hw(fmaf(p.x, xc, p.y)), p.z, acc[2]);
                acc[3] = fmaf(tanh_hw(fmaf(p.x, xd, p.y)), p.z, acc[3]);
            }
        }
    }

    // ---- partial sums -> smem: red[row_local][ol][es] ----
    #pragma unroll
    for (int k = 0; k < 4; k++)
        red[(((rg * 4 + k) * O_TILE) + ol) * ES + es] = acc[k];
    __syncthreads();

    // ---- final reduce: thread t owns output (row_local = t>>3, ol = t&7) ----
    {
        const int row_l = tid >> 3;
        const int olf   = tid & 7;
        float4 pv = *reinterpret_cast<const float4*>(&red[((row_l * O_TILE) + olf) * ES]);
        float s = (pv.x + pv.y) + (pv.z + pv.w);
        gout[(row0 + row_l) * O_DIM + o0 + olf] = s;
    }
}

extern "C" void kernel_launch(void* const* d_in, const int* in_sizes, int n_in,
                              void* d_out, int out_size) {
    const float* x = (const float*)d_in[0];
    const float* w = (const float*)d_in[1];
    const float* h = (const float*)d_in[2];
    const float* b = (const float*)d_in[3];
    float* out = (float*)d_out;

    cudaFuncSetAttribute(kan_kernel, cudaFuncAttributeMaxDynamicSharedMemorySize,
                         SMEM_BYTES);
    kan_kernel<<<NBLOCKS, THREADS, SMEM_BYTES>>>(x, w, h, b, out);
}